// round 15
// baseline (speedup 1.0000x reference)
#include <cuda_runtime.h>
#include <cstdint>
#include <cstddef>

// ---------------------------------------------------------------------------
// Bidirectional LSTM (Round 15 = R10 base + intra-CTA 2-seq anti-phase pipe):
//   1) prepass_kernel: gx = b_lstm + W_ih.(W_enc.x + b_enc) for all t
//      (parallel GEMM), 2 x 1GB staging, dir=1 stored t-reversed. (R10 verbatim)
//   2) recur_kernel: 256 CTAs, 2 seqs/CTA, 2 CTAs/SM. The two sequences are
//      software-pipelined in anti-phase: each tick = matmul(seq s, t) on all
//      256 threads CONCURRENT with epilogue(seq s^1) on tid<64, one
//      __syncthreads per tick. Epilogue latency hides under the other
//      sequence's matmul. Static seq indices via 2-tick unroll.
//   3) final_kernel.
// ---------------------------------------------------------------------------

#define T_STEPS 4096
#define HID     64
#define KIN     60
#define ENC     32

__device__ float g_gx0[256ULL * T_STEPS * 256];   // 1 GB, dir 0
__device__ float g_gx1[256ULL * T_STEPS * 256];   // 1 GB, dir 1 (reversed t)
__device__ float g_cfin[2][256][HID];

typedef unsigned long long ull;

__device__ __forceinline__ ull pack2(float lo, float hi) {
    ull u;
    asm("mov.b64 %0, {%1, %2};" : "=l"(u) : "f"(lo), "f"(hi));
    return u;
}
__device__ __forceinline__ void unpack2(ull u, float& lo, float& hi) {
    asm("mov.b64 {%0, %1}, %2;" : "=f"(lo), "=f"(hi) : "l"(u));
}
__device__ __forceinline__ void ffma2(ull& d, ull a, ull b) {
    asm("fma.rn.f32x2 %0, %1, %2, %0;" : "+l"(d) : "l"(a), "l"(b));
}
__device__ __forceinline__ float fast_sigmoid(float x) {
    return __fdividef(1.0f, 1.0f + __expf(-x));
}
__device__ __forceinline__ float fast_tanh(float x) {
    return 1.0f - __fdividef(2.0f, __expf(2.0f * x) + 1.0f);
}

__global__ void pad_kernel() {}

// ---------------------------------------------------------------------------
// Prepass (R10 verbatim): grid 2048 = (b:256) x (chunk:8 of 512 t).
// ---------------------------------------------------------------------------
__global__ void __launch_bounds__(256, 2)
prepass_kernel(const float* __restrict__ cin,
               const float* __restrict__ W_enc, const float* __restrict__ b_enc,
               const float* __restrict__ W_ih_f, const float* __restrict__ b_f,
               const float* __restrict__ W_ih_b, const float* __restrict__ b_b) {
    const int b     = blockIdx.x >> 3;
    const int chunk = blockIdx.x & 7;
    const int t0    = chunk * 512;
    const int tid   = threadIdx.x;
    const int dg    = tid >> 7;
    const int lt    = tid & 127;
    const int r0    = 2 * lt;

    __shared__ __align__(16) float  c_sm[64][KIN];
    __shared__ __align__(16) float  enc_sm[64][ENC];
    __shared__ __align__(8)  float2 wT[30][ENC];

    const float* W_ih = dg ? W_ih_b : W_ih_f;
    const float* bv   = dg ? b_b    : b_f;
    float* gxbase     = dg ? g_gx1  : g_gx0;

    ull wi0[16], wi1[16];
#pragma unroll
    for (int i = 0; i < 16; i++) {
        float2 p = *reinterpret_cast<const float2*>(W_ih + (size_t)r0 * ENC + 2 * i);
        float2 q = *reinterpret_cast<const float2*>(W_ih + (size_t)(r0 + 1) * ENC + 2 * i);
        wi0[i] = pack2(p.x, p.y);
        wi1[i] = pack2(q.x, q.y);
    }
    const float bias0 = bv[r0];
    const float bias1 = bv[r0 + 1];

    for (int idx = tid; idx < 30 * ENC; idx += 256) {
        const int i = idx >> 5, e = idx & 31;
        wT[i][e] = make_float2(W_enc[e * KIN + 2 * i], W_enc[e * KIN + 2 * i + 1]);
    }
    const float benc  = b_enc[tid & 31];
    const int   ewarp = tid >> 5;
    const int   ej    = tid & 31;

    for (int ss = 0; ss < 8; ss++) {
        const int tb = t0 + ss * 64;
        __syncthreads();
        {
            const float* src = cin + ((size_t)b * T_STEPS + tb) * KIN;
            for (int i = tid; i < 64 * KIN; i += 256)
                (&c_sm[0][0])[i] = src[i];
        }
        __syncthreads();

#pragma unroll
        for (int tt = 0; tt < 8; tt++) {
            const int t = ewarp * 8 + tt;
            ull acc = 0ull;
            const float* crow = &c_sm[t][0];
#pragma unroll
            for (int i = 0; i < 15; i++) {
                const ulonglong2 v = *reinterpret_cast<const ulonglong2*>(crow + 4 * i);
                ffma2(acc, *reinterpret_cast<const ull*>(&wT[2 * i][ej]), v.x);
                ffma2(acc, *reinterpret_cast<const ull*>(&wT[2 * i + 1][ej]), v.y);
            }
            float l, h;
            unpack2(acc, l, h);
            enc_sm[t][ej] = benc + l + h;
        }
        __syncthreads();

        for (int tt = 0; tt < 64; tt++) {
            ull a0 = pack2(bias0, 0.0f);
            ull a1 = pack2(bias1, 0.0f);
            const float* erow = &enc_sm[tt][0];
#pragma unroll
            for (int c = 0; c < 8; c++) {
                const ulonglong2 v = *reinterpret_cast<const ulonglong2*>(erow + 4 * c);
                ffma2(a0, wi0[2 * c], v.x); ffma2(a0, wi0[2 * c + 1], v.y);
                ffma2(a1, wi1[2 * c], v.x); ffma2(a1, wi1[2 * c + 1], v.y);
            }
            const int t = tb + tt;
            const int n = dg ? (T_STEPS - 1 - t) : t;
            float l0, h0, l1, h1;
            unpack2(a0, l0, h0);
            unpack2(a1, l1, h1);
            *reinterpret_cast<float2*>(gxbase + ((size_t)b * T_STEPS + n) * 256 + r0) =
                make_float2(l0 + h0, l1 + h1);
        }
    }
}

// ---------------------------------------------------------------------------
// Recurrent: grid 256 = (dir:2) x (bg:128 pairs), block 256, 2 CTAs/SM.
//   Tick pipeline: matmul(seq s, t) on all threads || epilogue(seq s^1) on
//   tid<64; one __syncthreads per tick; 2 ticks per timestep.
// ---------------------------------------------------------------------------
__global__ void __launch_bounds__(256, 2)
recur_kernel(const float* __restrict__ W_hh_f,
             const float* __restrict__ W_hh_b) {
    const int dir = blockIdx.x >> 7;
    const int bg  = blockIdx.x & 127;
    const int tid = threadIdx.x;
    const int kh  = tid >> 7;          // k-half: h dims [32kh, 32kh+32)
    const int rh  = tid & 127;
    const int r0  = 2 * rh;            // 2 gate rows

    __shared__ __align__(16) float hbuf[2][HID];     // h_t per seq
    __shared__ __align__(8)  float gps[2][2][256];   // partials [seq][kh][gate]

    const float* W_hh = dir ? W_hh_b : W_hh_f;

    // Wh rows r0, r0+1 over k in [kh*32, kh*32+32): 16 pairs each (64 regs)
    ull wh0[16], wh1[16];
#pragma unroll
    for (int i = 0; i < 16; i++) {
        float2 p = *reinterpret_cast<const float2*>(W_hh + (size_t)r0 * HID + kh * 32 + 2 * i);
        float2 q = *reinterpret_cast<const float2*>(W_hh + (size_t)(r0 + 1) * HID + kh * 32 + 2 * i);
        wh0[i] = pack2(p.x, p.y);
        wh1[i] = pack2(q.x, q.y);
    }

    // gx stream for the epilogue threads (tid<64): 4 scalar lanes per seq
    const float* gxb = dir ? g_gx1 : g_gx0;
    const float* gp0 = gxb + ((size_t)(bg * 2 + 0) * T_STEPS) * 256 + tid;
    const float* gp1 = gxb + ((size_t)(bg * 2 + 1) * T_STEPS) * 256 + tid;

    float gx00 = 0.f, gx01 = 0.f, gx02 = 0.f, gx03 = 0.f;   // seq0, gx(t)
    float gx10 = 0.f, gx11 = 0.f, gx12 = 0.f, gx13 = 0.f;   // seq1, gx(t)
    if (tid < 64) {
        gx00 = __ldg(gp0);       gx01 = __ldg(gp0 + 64);
        gx02 = __ldg(gp0 + 128); gx03 = __ldg(gp0 + 192);
        gx10 = __ldg(gp1);       gx11 = __ldg(gp1 + 64);
        gx12 = __ldg(gp1 + 128); gx13 = __ldg(gp1 + 192);
        gp0 += 256;
        gp1 += 256;
    }
    float cs0 = 0.0f, cs1 = 0.0f;
    if (tid < 128) hbuf[tid >> 6][tid & 63] = 0.0f;
    __syncthreads();

    // matmul for one seq: 2 rows x 32 dims, result -> gps[S]
#define MATMUL(S)                                                              \
    {                                                                          \
        ull aA = 0ull, aB = 0ull;                                              \
        const float* hb = &hbuf[S][kh * 32];                                   \
        _Pragma("unroll")                                                      \
        for (int c = 0; c < 8; c++) {                                          \
            const ulonglong2 v = *reinterpret_cast<const ulonglong2*>(hb + 4 * c); \
            ffma2(aA, wh0[2 * c], v.x); ffma2(aA, wh0[2 * c + 1], v.y);        \
            ffma2(aB, wh1[2 * c], v.x); ffma2(aB, wh1[2 * c + 1], v.y);        \
        }                                                                      \
        float lA, hA, lB, hB;                                                  \
        unpack2(aA, lA, hA);                                                   \
        unpack2(aB, lB, hB);                                                   \
        *reinterpret_cast<float2*>(&gps[S][kh][r0]) = make_float2(lA + hA, lB + hB); \
    }

    // epilogue for one seq (tid<64): consume gps[S] + gx regs, update cell,
    // publish h; prefetch gx(t+1) (consumed 2 ticks later).
#define EPIL(S, GX0, GX1, GX2, GX3, CS, GP, TCUR)                              \
    if (tid < 64) {                                                            \
        const float gi = gps[S][0][tid]       + gps[S][1][tid]       + GX0;    \
        const float gf = gps[S][0][64 + tid]  + gps[S][1][64 + tid]  + GX1;    \
        const float gg = gps[S][0][128 + tid] + gps[S][1][128 + tid] + GX2;    \
        const float go = gps[S][0][192 + tid] + gps[S][1][192 + tid] + GX3;    \
        if ((TCUR) + 1 < T_STEPS) {                                            \
            GX0 = __ldg(GP);       GX1 = __ldg(GP + 64);                       \
            GX2 = __ldg(GP + 128); GX3 = __ldg(GP + 192);                      \
            GP += 256;                                                         \
        }                                                                      \
        const float ig = fast_sigmoid(gi);                                     \
        const float fg = fast_sigmoid(gf);                                     \
        const float og = fast_sigmoid(go);                                     \
        const float gt = fast_tanh(gg);                                        \
        CS = fg * CS + ig * gt;                                                \
        hbuf[S][tid] = og * fast_tanh(CS);                                     \
    }

    // tick 0: matmul(seq0, t=0)
    MATMUL(0);
    __syncthreads();

    for (int t = 0; t < T_STEPS; t++) {
        // tick 2t+1: matmul(seq1, t) || epilogue(seq0, t)
        EPIL(0, gx00, gx01, gx02, gx03, cs0, gp0, t);
        MATMUL(1);
        __syncthreads();

        // tick 2t+2: matmul(seq0, t+1) || epilogue(seq1, t)
        EPIL(1, gx10, gx11, gx12, gx13, cs1, gp1, t);
        if (t + 1 < T_STEPS) MATMUL(0);
        __syncthreads();
    }
#undef MATMUL
#undef EPIL

    if (tid < 64) {
        g_cfin[dir][bg * 2 + 0][tid] = cs0;
        g_cfin[dir][bg * 2 + 1][tid] = cs1;
    }
}

// ---------------------------------------------------------------------------
__global__ void final_kernel(const float* __restrict__ W_fin,
                             const float* __restrict__ b_fin,
                             float* __restrict__ out) {
    const int b = threadIdx.x;
    float a0 = b_fin[0], a1 = b_fin[1], a2 = b_fin[2];
#pragma unroll
    for (int j = 0; j < HID; j++) {
        const float cf = g_cfin[0][b][j];
        a0 += W_fin[0 * 128 + j] * cf;
        a1 += W_fin[1 * 128 + j] * cf;
        a2 += W_fin[2 * 128 + j] * cf;
    }
#pragma unroll
    for (int j = 0; j < HID; j++) {
        const float cb = g_cfin[1][b][j];
        a0 += W_fin[0 * 128 + 64 + j] * cb;
        a1 += W_fin[1 * 128 + 64 + j] * cb;
        a2 += W_fin[2 * 128 + 64 + j] * cb;
    }
    out[b * 3 + 0] = a0;
    out[b * 3 + 1] = a1;
    out[b * 3 + 2] = a2;
}

extern "C" void kernel_launch(void* const* d_in, const int* in_sizes, int n_in,
                              void* d_out, int out_size) {
    (void)in_sizes; (void)n_in; (void)out_size;
    const float* c      = (const float*)d_in[0];
    const float* W_enc  = (const float*)d_in[1];
    const float* b_enc  = (const float*)d_in[2];
    const float* W_ih_f = (const float*)d_in[3];
    const float* W_hh_f = (const float*)d_in[4];
    const float* b_f    = (const float*)d_in[5];
    const float* W_ih_b = (const float*)d_in[6];
    const float* W_hh_b = (const float*)d_in[7];
    const float* b_b    = (const float*)d_in[8];
    const float* W_fin  = (const float*)d_in[9];
    const float* b_fin  = (const float*)d_in[10];
    float* out = (float*)d_out;

    prepass_kernel<<<2048, 256>>>(c, W_enc, b_enc, W_ih_f, b_f, W_ih_b, b_b);
    pad_kernel<<<1, 32>>>();
    pad_kernel<<<1, 32>>>();
    recur_kernel<<<256, 256>>>(W_hh_f, W_hh_b);
    final_kernel<<<1, 256>>>(W_fin, b_fin, out);
}

// round 16
// speedup vs baseline: 1.4310x; 1.4310x over previous
#include <cuda_runtime.h>
#include <cstdint>
#include <cstddef>

// ---------------------------------------------------------------------------
// Bidirectional LSTM (Round 16 = R10 + gx staging moved to idle threads):
//   1) prepass_kernel: gx = b_lstm + W_ih.(W_enc.x + b_enc) for all t
//      (parallel GEMM), 2 x 1GB staging, dir=1 stored t-reversed. (R10 verbatim)
//   2) recur_kernel: 256 CTAs, 2 seqs/CTA, 2 CTAs/SM, thread = 2 gate rows x
//      32-h k-half x 2 seqs (R10 shape). NEW: gx is staged into a 2-slot smem
//      ring by the phase-B-idle threads (tid>=128) from registers loaded one
//      step ahead; the epilogue (tid<128) reads smem only — no LDG, fewer
//      regs, shorter phase-B critical path.
//   3) final_kernel.
// ---------------------------------------------------------------------------

#define T_STEPS 4096
#define HID     64
#define KIN     60
#define ENC     32

__device__ float g_gx0[256ULL * T_STEPS * 256];   // 1 GB, dir 0
__device__ float g_gx1[256ULL * T_STEPS * 256];   // 1 GB, dir 1 (reversed t)
__device__ float g_cfin[2][256][HID];

typedef unsigned long long ull;

__device__ __forceinline__ ull pack2(float lo, float hi) {
    ull u;
    asm("mov.b64 %0, {%1, %2};" : "=l"(u) : "f"(lo), "f"(hi));
    return u;
}
__device__ __forceinline__ void unpack2(ull u, float& lo, float& hi) {
    asm("mov.b64 {%0, %1}, %2;" : "=f"(lo), "=f"(hi) : "l"(u));
}
__device__ __forceinline__ void ffma2(ull& d, ull a, ull b) {
    asm("fma.rn.f32x2 %0, %1, %2, %0;" : "+l"(d) : "l"(a), "l"(b));
}
__device__ __forceinline__ float fast_sigmoid(float x) {
    return __fdividef(1.0f, 1.0f + __expf(-x));
}
__device__ __forceinline__ float fast_tanh(float x) {
    return 1.0f - __fdividef(2.0f, __expf(2.0f * x) + 1.0f);
}

__global__ void pad_kernel() {}

// ---------------------------------------------------------------------------
// Prepass (R10 verbatim): grid 2048 = (b:256) x (chunk:8 of 512 t).
// ---------------------------------------------------------------------------
__global__ void __launch_bounds__(256, 2)
prepass_kernel(const float* __restrict__ cin,
               const float* __restrict__ W_enc, const float* __restrict__ b_enc,
               const float* __restrict__ W_ih_f, const float* __restrict__ b_f,
               const float* __restrict__ W_ih_b, const float* __restrict__ b_b) {
    const int b     = blockIdx.x >> 3;
    const int chunk = blockIdx.x & 7;
    const int t0    = chunk * 512;
    const int tid   = threadIdx.x;
    const int dg    = tid >> 7;
    const int lt    = tid & 127;
    const int r0    = 2 * lt;

    __shared__ __align__(16) float  c_sm[64][KIN];
    __shared__ __align__(16) float  enc_sm[64][ENC];
    __shared__ __align__(8)  float2 wT[30][ENC];

    const float* W_ih = dg ? W_ih_b : W_ih_f;
    const float* bv   = dg ? b_b    : b_f;
    float* gxbase     = dg ? g_gx1  : g_gx0;

    ull wi0[16], wi1[16];
#pragma unroll
    for (int i = 0; i < 16; i++) {
        float2 p = *reinterpret_cast<const float2*>(W_ih + (size_t)r0 * ENC + 2 * i);
        float2 q = *reinterpret_cast<const float2*>(W_ih + (size_t)(r0 + 1) * ENC + 2 * i);
        wi0[i] = pack2(p.x, p.y);
        wi1[i] = pack2(q.x, q.y);
    }
    const float bias0 = bv[r0];
    const float bias1 = bv[r0 + 1];

    for (int idx = tid; idx < 30 * ENC; idx += 256) {
        const int i = idx >> 5, e = idx & 31;
        wT[i][e] = make_float2(W_enc[e * KIN + 2 * i], W_enc[e * KIN + 2 * i + 1]);
    }
    const float benc  = b_enc[tid & 31];
    const int   ewarp = tid >> 5;
    const int   ej    = tid & 31;

    for (int ss = 0; ss < 8; ss++) {
        const int tb = t0 + ss * 64;
        __syncthreads();
        {
            const float* src = cin + ((size_t)b * T_STEPS + tb) * KIN;
            for (int i = tid; i < 64 * KIN; i += 256)
                (&c_sm[0][0])[i] = src[i];
        }
        __syncthreads();

#pragma unroll
        for (int tt = 0; tt < 8; tt++) {
            const int t = ewarp * 8 + tt;
            ull acc = 0ull;
            const float* crow = &c_sm[t][0];
#pragma unroll
            for (int i = 0; i < 15; i++) {
                const ulonglong2 v = *reinterpret_cast<const ulonglong2*>(crow + 4 * i);
                ffma2(acc, *reinterpret_cast<const ull*>(&wT[2 * i][ej]), v.x);
                ffma2(acc, *reinterpret_cast<const ull*>(&wT[2 * i + 1][ej]), v.y);
            }
            float l, h;
            unpack2(acc, l, h);
            enc_sm[t][ej] = benc + l + h;
        }
        __syncthreads();

        for (int tt = 0; tt < 64; tt++) {
            ull a0 = pack2(bias0, 0.0f);
            ull a1 = pack2(bias1, 0.0f);
            const float* erow = &enc_sm[tt][0];
#pragma unroll
            for (int c = 0; c < 8; c++) {
                const ulonglong2 v = *reinterpret_cast<const ulonglong2*>(erow + 4 * c);
                ffma2(a0, wi0[2 * c], v.x); ffma2(a0, wi0[2 * c + 1], v.y);
                ffma2(a1, wi1[2 * c], v.x); ffma2(a1, wi1[2 * c + 1], v.y);
            }
            const int t = tb + tt;
            const int n = dg ? (T_STEPS - 1 - t) : t;
            float l0, h0, l1, h1;
            unpack2(a0, l0, h0);
            unpack2(a1, l1, h1);
            *reinterpret_cast<float2*>(gxbase + ((size_t)b * T_STEPS + n) * 256 + r0) =
                make_float2(l0 + h0, l1 + h1);
        }
    }
}

// ---------------------------------------------------------------------------
// Recurrent: grid 256 = (dir:2) x (bg:128 pairs), block 256, 2 CTAs/SM.
//   R10 shape + smem gx ring filled by tid>=128 during phase B.
// ---------------------------------------------------------------------------
__global__ void __launch_bounds__(256, 2)
recur_kernel(const float* __restrict__ W_hh_f,
             const float* __restrict__ W_hh_b) {
    const int dir = blockIdx.x >> 7;
    const int bg  = blockIdx.x & 127;
    const int tid = threadIdx.x;
    const int kh  = tid >> 7;          // k-half: h dims [32kh, 32kh+32)
    const int rh  = tid & 127;
    const int r0  = 2 * rh;            // 2 gate rows

    __shared__ __align__(16) float hbuf[2][HID];      // h_t per seq
    __shared__ __align__(8)  float gps[2][2][256];    // Wh partials [seq][kh]
    __shared__ __align__(8)  float gxs[2][2][256];    // gx ring [slot][seq]

    const float* W_hh = dir ? W_hh_b : W_hh_f;

    // Wh rows r0, r0+1 over k in [kh*32, kh*32+32): 16 pairs each (64 regs)
    ull wh0[16], wh1[16];
#pragma unroll
    for (int i = 0; i < 16; i++) {
        float2 p = *reinterpret_cast<const float2*>(W_hh + (size_t)r0 * HID + kh * 32 + 2 * i);
        float2 q = *reinterpret_cast<const float2*>(W_hh + (size_t)(r0 + 1) * HID + kh * 32 + 2 * i);
        wh0[i] = pack2(p.x, p.y);
        wh1[i] = pack2(q.x, q.y);
    }

    // ---- gx loader mapping (tid >= 128): 4 gate values of one seq ----
    const int  lix  = tid & 127;       // 0..127
    const int  lseq = lix >> 6;        // seq 0/1
    const int  lj   = lix & 63;        // gate lane (i/f/g/o at +0/64/128/192)
    const float* gxb = dir ? g_gx1 : g_gx0;
    const float* gpl = gxb + ((size_t)(bg * 2 + lseq) * T_STEPS) * 256 + lj;

    float gl0 = 0.f, gl1 = 0.f, gl2 = 0.f, gl3 = 0.f;   // regs: gx(t+1)
    if (tid >= 128) {
        // prologue: gxs[0] <- gx(0); regs <- gx(1)
        gxs[0][lseq][lj]       = __ldg(gpl);
        gxs[0][lseq][64 + lj]  = __ldg(gpl + 64);
        gxs[0][lseq][128 + lj] = __ldg(gpl + 128);
        gxs[0][lseq][192 + lj] = __ldg(gpl + 192);
        gl0 = __ldg(gpl + 256);       gl1 = __ldg(gpl + 256 + 64);
        gl2 = __ldg(gpl + 256 + 128); gl3 = __ldg(gpl + 256 + 192);
        gpl += 2 * 256;               // points at gx(2)
    }

    const int s_ep = tid >> 6;         // epilogue mapping (tid<128)
    const int j_ep = tid & 63;
    float cst = 0.0f;
    if (tid < 128) hbuf[s_ep][j_ep] = 0.0f;
    __syncthreads();

    for (int t = 0; t < T_STEPS; t++) {
        // ================= phase A: Wh . h(t) partials =================
#pragma unroll
        for (int s = 0; s < 2; s++) {
            ull aA = 0ull, aB = 0ull;
            const float* hb = &hbuf[s][kh * 32];
#pragma unroll
            for (int c = 0; c < 8; c++) {
                const ulonglong2 v = *reinterpret_cast<const ulonglong2*>(hb + 4 * c);
                ffma2(aA, wh0[2 * c], v.x); ffma2(aA, wh0[2 * c + 1], v.y);
                ffma2(aB, wh1[2 * c], v.x); ffma2(aB, wh1[2 * c + 1], v.y);
            }
            float lA, hA, lB, hB;
            unpack2(aA, lA, hA);
            unpack2(aB, lB, hB);
            *reinterpret_cast<float2*>(&gps[s][kh][r0]) = make_float2(lA + hA, lB + hB);
        }
        __syncthreads();   // BAR A: gps(t) ready; hbuf reads retired

        // ================= phase B =================
        if (tid < 128) {
            // epilogue: 1 cell, gates = Wh partials + staged gx
            const float* gx = &gxs[t & 1][s_ep][0];
            const float gi = gps[s_ep][0][j_ep]       + gps[s_ep][1][j_ep]       + gx[j_ep];
            const float gf = gps[s_ep][0][64 + j_ep]  + gps[s_ep][1][64 + j_ep]  + gx[64 + j_ep];
            const float gg = gps[s_ep][0][128 + j_ep] + gps[s_ep][1][128 + j_ep] + gx[128 + j_ep];
            const float go = gps[s_ep][0][192 + j_ep] + gps[s_ep][1][192 + j_ep] + gx[192 + j_ep];

            const float ig = fast_sigmoid(gi);
            const float fg = fast_sigmoid(gf);
            const float og = fast_sigmoid(go);
            const float gt = fast_tanh(gg);
            cst = fg * cst + ig * gt;
            hbuf[s_ep][j_ep] = og * fast_tanh(cst);
        } else {
            // loaders: publish gx(t+1) from regs; fetch gx(t+2)
            if (t + 1 < T_STEPS) {
                const int sl = (t + 1) & 1;
                gxs[sl][lseq][lj]       = gl0;
                gxs[sl][lseq][64 + lj]  = gl1;
                gxs[sl][lseq][128 + lj] = gl2;
                gxs[sl][lseq][192 + lj] = gl3;
            }
            if (t + 2 < T_STEPS) {
                gl0 = __ldg(gpl);       gl1 = __ldg(gpl + 64);
                gl2 = __ldg(gpl + 128); gl3 = __ldg(gpl + 192);
                gpl += 256;
            }
        }
        __syncthreads();   // BAR B: h(t+1) + gxs slot published
    }

    if (tid < 128) g_cfin[dir][bg * 2 + s_ep][j_ep] = cst;
}

// ---------------------------------------------------------------------------
__global__ void final_kernel(const float* __restrict__ W_fin,
                             const float* __restrict__ b_fin,
                             float* __restrict__ out) {
    const int b = threadIdx.x;
    float a0 = b_fin[0], a1 = b_fin[1], a2 = b_fin[2];
#pragma unroll
    for (int j = 0; j < HID; j++) {
        const float cf = g_cfin[0][b][j];
        a0 += W_fin[0 * 128 + j] * cf;
        a1 += W_fin[1 * 128 + j] * cf;
        a2 += W_fin[2 * 128 + j] * cf;
    }
#pragma unroll
    for (int j = 0; j < HID; j++) {
        const float cb = g_cfin[1][b][j];
        a0 += W_fin[0 * 128 + 64 + j] * cb;
        a1 += W_fin[1 * 128 + 64 + j] * cb;
        a2 += W_fin[2 * 128 + 64 + j] * cb;
    }
    out[b * 3 + 0] = a0;
    out[b * 3 + 1] = a1;
    out[b * 3 + 2] = a2;
}

extern "C" void kernel_launch(void* const* d_in, const int* in_sizes, int n_in,
                              void* d_out, int out_size) {
    (void)in_sizes; (void)n_in; (void)out_size;
    const float* c      = (const float*)d_in[0];
    const float* W_enc  = (const float*)d_in[1];
    const float* b_enc  = (const float*)d_in[2];
    const float* W_ih_f = (const float*)d_in[3];
    const float* W_hh_f = (const float*)d_in[4];
    const float* b_f    = (const float*)d_in[5];
    const float* W_ih_b = (const float*)d_in[6];
    const float* W_hh_b = (const float*)d_in[7];
    const float* b_b    = (const float*)d_in[8];
    const float* W_fin  = (const float*)d_in[9];
    const float* b_fin  = (const float*)d_in[10];
    float* out = (float*)d_out;

    prepass_kernel<<<2048, 256>>>(c, W_enc, b_enc, W_ih_f, b_f, W_ih_b, b_b);
    pad_kernel<<<1, 32>>>();
    pad_kernel<<<1, 32>>>();
    recur_kernel<<<256, 256>>>(W_hh_f, W_hh_b);
    final_kernel<<<1, 256>>>(W_fin, b_fin, out);
}

// round 17
// speedup vs baseline: 1.7494x; 1.2225x over previous
#include <cuda_runtime.h>
#include <cstdint>
#include <cstddef>

// ---------------------------------------------------------------------------
// Bidirectional LSTM (Round 17 = R10 recur verbatim + pipelined prepass):
//   1) prepass_kernel: gx = b_lstm + W_ih.(W_enc.x + b_enc) for all t.
//      NEW: c_sm double-buffered; c(ss+1) loaded (float4) DURING gx(ss) so
//      DRAM latency hides under FMA work; 2 barriers/subtile (was 3);
//      enc stage uses 2 interleaved accumulators (halves chain stall).
//   2) recur_kernel: BYTE-IDENTICAL to Round 10 (best measured: 2370 us).
//   3) final_kernel.
// ---------------------------------------------------------------------------

#define T_STEPS 4096
#define HID     64
#define KIN     60
#define ENC     32

__device__ float g_gx0[256ULL * T_STEPS * 256];   // 1 GB, dir 0
__device__ float g_gx1[256ULL * T_STEPS * 256];   // 1 GB, dir 1 (reversed t)
__device__ float g_cfin[2][256][HID];

typedef unsigned long long ull;

__device__ __forceinline__ ull pack2(float lo, float hi) {
    ull u;
    asm("mov.b64 %0, {%1, %2};" : "=l"(u) : "f"(lo), "f"(hi));
    return u;
}
__device__ __forceinline__ void unpack2(ull u, float& lo, float& hi) {
    asm("mov.b64 {%0, %1}, %2;" : "=f"(lo), "=f"(hi) : "l"(u));
}
__device__ __forceinline__ void ffma2(ull& d, ull a, ull b) {
    asm("fma.rn.f32x2 %0, %1, %2, %0;" : "+l"(d) : "l"(a), "l"(b));
}
__device__ __forceinline__ float fast_sigmoid(float x) {
    return __fdividef(1.0f, 1.0f + __expf(-x));
}
__device__ __forceinline__ float fast_tanh(float x) {
    return 1.0f - __fdividef(2.0f, __expf(2.0f * x) + 1.0f);
}

__global__ void pad_kernel() {}

// ---------------------------------------------------------------------------
// Prepass: grid 2048 = (b:256) x (chunk:8 of 512 t), block 256, 2 CTAs/SM.
//   Per 64-t subtile: enc(ss); bar; { gx(ss) || float4-load c(ss+1) }; bar.
// ---------------------------------------------------------------------------
__global__ void __launch_bounds__(256, 2)
prepass_kernel(const float* __restrict__ cin,
               const float* __restrict__ W_enc, const float* __restrict__ b_enc,
               const float* __restrict__ W_ih_f, const float* __restrict__ b_f,
               const float* __restrict__ W_ih_b, const float* __restrict__ b_b) {
    const int b     = blockIdx.x >> 3;
    const int chunk = blockIdx.x & 7;
    const int t0    = chunk * 512;
    const int tid   = threadIdx.x;
    const int dg    = tid >> 7;        // direction group
    const int lt    = tid & 127;
    const int r0    = 2 * lt;          // 2 gate rows

    __shared__ __align__(16) float  c_sm[2][64][KIN];   // 30720 B (double buf)
    __shared__ __align__(16) float  enc_sm[64][ENC];    //  8192 B
    __shared__ __align__(8)  float2 wT[30][ENC];        //  7680 B

    const float* W_ih = dg ? W_ih_b : W_ih_f;
    const float* bv   = dg ? b_b    : b_f;
    float* gxbase     = dg ? g_gx1  : g_gx0;

    // W_ih rows r0, r0+1 into regs (16 pairs each)
    ull wi0[16], wi1[16];
#pragma unroll
    for (int i = 0; i < 16; i++) {
        float2 p = *reinterpret_cast<const float2*>(W_ih + (size_t)r0 * ENC + 2 * i);
        float2 q = *reinterpret_cast<const float2*>(W_ih + (size_t)(r0 + 1) * ENC + 2 * i);
        wi0[i] = pack2(p.x, p.y);
        wi1[i] = pack2(q.x, q.y);
    }
    const float bias0 = bv[r0];
    const float bias1 = bv[r0 + 1];

    // transposed encoder weights: wT[i][e] = (W_enc[e][2i], W_enc[e][2i+1])
    for (int idx = tid; idx < 30 * ENC; idx += 256) {
        const int i = idx >> 5, e = idx & 31;
        wT[i][e] = make_float2(W_enc[e * KIN + 2 * i], W_enc[e * KIN + 2 * i + 1]);
    }
    const float benc  = b_enc[tid & 31];
    const int   ewarp = tid >> 5;      // 8 warps x 8 t's
    const int   ej    = tid & 31;      // enc row

    // preload c(subtile 0) into buffer 0 (float4: 960 per subtile)
    {
        const float4* src = reinterpret_cast<const float4*>(
            cin + ((size_t)b * T_STEPS + t0) * KIN);
        float4* dst = reinterpret_cast<float4*>(&c_sm[0][0][0]);
        for (int i = tid; i < 64 * KIN / 4; i += 256) dst[i] = src[i];
    }
    __syncthreads();

    for (int ss = 0; ss < 8; ss++) {
        const int tb  = t0 + ss * 64;
        const int cur = ss & 1;

        // ---- enc(ss): warp ewarp handles t = ewarp*8 + tt (2-acc interleave)
#pragma unroll
        for (int tt = 0; tt < 8; tt += 2) {
            const int t0i = ewarp * 8 + tt;
            ull accA = 0ull, accB = 0ull;
            const float* crowA = &c_sm[cur][t0i][0];
            const float* crowB = &c_sm[cur][t0i + 1][0];
#pragma unroll
            for (int i = 0; i < 15; i++) {
                const ulonglong2 vA = *reinterpret_cast<const ulonglong2*>(crowA + 4 * i);
                const ulonglong2 vB = *reinterpret_cast<const ulonglong2*>(crowB + 4 * i);
                ffma2(accA, *reinterpret_cast<const ull*>(&wT[2 * i][ej]), vA.x);
                ffma2(accB, *reinterpret_cast<const ull*>(&wT[2 * i][ej]), vB.x);
                ffma2(accA, *reinterpret_cast<const ull*>(&wT[2 * i + 1][ej]), vA.y);
                ffma2(accB, *reinterpret_cast<const ull*>(&wT[2 * i + 1][ej]), vB.y);
            }
            float l, h;
            unpack2(accA, l, h);
            enc_sm[t0i][ej] = benc + l + h;
            unpack2(accB, l, h);
            enc_sm[t0i + 1][ej] = benc + l + h;
        }
        __syncthreads();   // enc_sm(ss) ready; c_sm[cur] reads retired

        // ---- gx(ss) from enc_sm  ||  load c(ss+1) into the other buffer ----
        if (ss + 1 < 8) {
            const float4* src = reinterpret_cast<const float4*>(
                cin + ((size_t)b * T_STEPS + tb + 64) * KIN);
            float4* dst = reinterpret_cast<float4*>(&c_sm[cur ^ 1][0][0]);
            for (int i = tid; i < 64 * KIN / 4; i += 256) dst[i] = src[i];
        }
        for (int tt = 0; tt < 64; tt++) {
            ull a0 = pack2(bias0, 0.0f);
            ull a1 = pack2(bias1, 0.0f);
            const float* erow = &enc_sm[tt][0];
#pragma unroll
            for (int c = 0; c < 8; c++) {
                const ulonglong2 v = *reinterpret_cast<const ulonglong2*>(erow + 4 * c);
                ffma2(a0, wi0[2 * c], v.x); ffma2(a0, wi0[2 * c + 1], v.y);
                ffma2(a1, wi1[2 * c], v.x); ffma2(a1, wi1[2 * c + 1], v.y);
            }
            const int t = tb + tt;
            const int n = dg ? (T_STEPS - 1 - t) : t;
            float l0, h0, l1, h1;
            unpack2(a0, l0, h0);
            unpack2(a1, l1, h1);
            *reinterpret_cast<float2*>(gxbase + ((size_t)b * T_STEPS + n) * 256 + r0) =
                make_float2(l0 + h0, l1 + h1);
        }
        __syncthreads();   // gx(ss) reads of enc_sm done; c(ss+1) staged
    }
}

// ---------------------------------------------------------------------------
// Recurrent (Round 10 verbatim): grid 256 = (dir:2) x (bg:128 pairs),
// block 256, 2 CTAs/SM. Thread = 2 gate rows x 32-h k-half x 2 seqs.
// ---------------------------------------------------------------------------
__global__ void __launch_bounds__(256, 2)
recur_kernel(const float* __restrict__ W_hh_f,
             const float* __restrict__ W_hh_b) {
    const int dir = blockIdx.x >> 7;
    const int bg  = blockIdx.x & 127;
    const int tid = threadIdx.x;
    const int kh  = tid >> 7;
    const int rh  = tid & 127;
    const int r0  = 2 * rh;

    __shared__ __align__(16) float hbuf[2][HID];     // h_t per seq
    __shared__ __align__(8)  float gps[2][2][256];   // partials [seq][kh][gate]

    const float* W_hh = dir ? W_hh_b : W_hh_f;

    ull wh0[16], wh1[16];
#pragma unroll
    for (int i = 0; i < 16; i++) {
        float2 p = *reinterpret_cast<const float2*>(W_hh + (size_t)r0 * HID + kh * 32 + 2 * i);
        float2 q = *reinterpret_cast<const float2*>(W_hh + (size_t)(r0 + 1) * HID + kh * 32 + 2 * i);
        wh0[i] = pack2(p.x, p.y);
        wh1[i] = pack2(q.x, q.y);
    }

    const float* gxb = dir ? g_gx1 : g_gx0;
    const float* gp0 = gxb + ((size_t)(bg * 2 + 0) * T_STEPS) * 256 + r0;
    const float* gp1 = gxb + ((size_t)(bg * 2 + 1) * T_STEPS) * 256 + r0;

    float2 gA0, gA1, gB0, gB1;
    gA0 = gA1 = gB0 = gB1 = make_float2(0.0f, 0.0f);
    if (kh == 0) {
        gA0 = *reinterpret_cast<const float2*>(gp0);
        gA1 = *reinterpret_cast<const float2*>(gp1);
        gB0 = *reinterpret_cast<const float2*>(gp0 + 256);
        gB1 = *reinterpret_cast<const float2*>(gp1 + 256);
    }

    const int s_ep = (tid >> 6) & 1;
    const int j_ep = tid & 63;
    float cst = 0.0f;
    if (tid < 128) hbuf[s_ep][j_ep] = 0.0f;
    __syncthreads();

#define STEP_BODY(TT, G0, G1)                                                  \
    {                                                                          \
        ull a0A = (kh == 0) ? pack2(G0.x, 0.0f) : 0ull;                        \
        ull a0B = (kh == 0) ? pack2(G0.y, 0.0f) : 0ull;                        \
        ull a1A = (kh == 0) ? pack2(G1.x, 0.0f) : 0ull;                        \
        ull a1B = (kh == 0) ? pack2(G1.y, 0.0f) : 0ull;                        \
        if (kh == 0 && (TT) + 2 < T_STEPS) {                                   \
            G0 = *reinterpret_cast<const float2*>(gp0 + (size_t)((TT) + 2) * 256); \
            G1 = *reinterpret_cast<const float2*>(gp1 + (size_t)((TT) + 2) * 256); \
        }                                                                      \
        const float* hb0 = &hbuf[0][kh * 32];                                  \
        const float* hb1 = &hbuf[1][kh * 32];                                  \
        _Pragma("unroll")                                                      \
        for (int c = 0; c < 8; c++) {                                          \
            const ulonglong2 v0 = *reinterpret_cast<const ulonglong2*>(hb0 + 4 * c); \
            const ulonglong2 v1 = *reinterpret_cast<const ulonglong2*>(hb1 + 4 * c); \
            ffma2(a0A, wh0[2 * c], v0.x); ffma2(a0A, wh0[2 * c + 1], v0.y);    \
            ffma2(a0B, wh1[2 * c], v0.x); ffma2(a0B, wh1[2 * c + 1], v0.y);    \
            ffma2(a1A, wh0[2 * c], v1.x); ffma2(a1A, wh0[2 * c + 1], v1.y);    \
            ffma2(a1B, wh1[2 * c], v1.x); ffma2(a1B, wh1[2 * c + 1], v1.y);    \
        }                                                                      \
        float l0, h0, l1, h1;                                                  \
        unpack2(a0A, l0, h0); unpack2(a0B, l1, h1);                            \
        *reinterpret_cast<float2*>(&gps[0][kh][r0]) = make_float2(l0 + h0, l1 + h1); \
        unpack2(a1A, l0, h0); unpack2(a1B, l1, h1);                            \
        *reinterpret_cast<float2*>(&gps[1][kh][r0]) = make_float2(l0 + h0, l1 + h1); \
        __syncthreads();                                                       \
        if (tid < 128) {                                                       \
            const float gi = gps[s_ep][0][j_ep]       + gps[s_ep][1][j_ep];    \
            const float gf = gps[s_ep][0][64 + j_ep]  + gps[s_ep][1][64 + j_ep];  \
            const float gg = gps[s_ep][0][128 + j_ep] + gps[s_ep][1][128 + j_ep]; \
            const float go = gps[s_ep][0][192 + j_ep] + gps[s_ep][1][192 + j_ep]; \
            const float ig = fast_sigmoid(gi);                                 \
            const float fg = fast_sigmoid(gf);                                 \
            const float og = fast_sigmoid(go);                                 \
            const float gt = fast_tanh(gg);                                    \
            cst = fg * cst + ig * gt;                                          \
            hbuf[s_ep][j_ep] = og * fast_tanh(cst);                            \
        }                                                                      \
        __syncthreads();                                                       \
    }

    for (int t = 0; t < T_STEPS; t += 2) {
        STEP_BODY(t, gA0, gA1);
        STEP_BODY(t + 1, gB0, gB1);
    }
#undef STEP_BODY

    if (tid < 128) g_cfin[dir][bg * 2 + s_ep][j_ep] = cst;
}

// ---------------------------------------------------------------------------
__global__ void final_kernel(const float* __restrict__ W_fin,
                             const float* __restrict__ b_fin,
                             float* __restrict__ out) {
    const int b = threadIdx.x;
    float a0 = b_fin[0], a1 = b_fin[1], a2 = b_fin[2];
#pragma unroll
    for (int j = 0; j < HID; j++) {
        const float cf = g_cfin[0][b][j];
        a0 += W_fin[0 * 128 + j] * cf;
        a1 += W_fin[1 * 128 + j] * cf;
        a2 += W_fin[2 * 128 + j] * cf;
    }
#pragma unroll
    for (int j = 0; j < HID; j++) {
        const float cb = g_cfin[1][b][j];
        a0 += W_fin[0 * 128 + 64 + j] * cb;
        a1 += W_fin[1 * 128 + 64 + j] * cb;
        a2 += W_fin[2 * 128 + 64 + j] * cb;
    }
    out[b * 3 + 0] = a0;
    out[b * 3 + 1] = a1;
    out[b * 3 + 2] = a2;
}

extern "C" void kernel_launch(void* const* d_in, const int* in_sizes, int n_in,
                              void* d_out, int out_size) {
    (void)in_sizes; (void)n_in; (void)out_size;
    const float* c      = (const float*)d_in[0];
    const float* W_enc  = (const float*)d_in[1];
    const float* b_enc  = (const float*)d_in[2];
    const float* W_ih_f = (const float*)d_in[3];
    const float* W_hh_f = (const float*)d_in[4];
    const float* b_f    = (const float*)d_in[5];
    const float* W_ih_b = (const float*)d_in[6];
    const float* W_hh_b = (const float*)d_in[7];
    const float* b_b    = (const float*)d_in[8];
    const float* W_fin  = (const float*)d_in[9];
    const float* b_fin  = (const float*)d_in[10];
    float* out = (float*)d_out;

    prepass_kernel<<<2048, 256>>>(c, W_enc, b_enc, W_ih_f, b_f, W_ih_b, b_b);
    pad_kernel<<<1, 32>>>();
    pad_kernel<<<1, 32>>>();
    recur_kernel<<<256, 256>>>(W_hh_f, W_hh_b);
    final_kernel<<<1, 256>>>(W_fin, b_fin, out);
}